// round 13
// baseline (speedup 1.0000x reference)
#include <cuda_runtime.h>
#include <cuda_fp16.h>
#include <cstdint>
#include <math.h>

// ---------------------------------------------------------------------------
// Problem constants
// ---------------------------------------------------------------------------
#define BS   2
#define NQ   16384
#define E    256
#define NH   8
#define NL   4
#define NP   4
#define TOTV 21760
#define NOUT 384
#define M_TOT (BS * NQ)

// convert quads (each thread processes 4 float4 = 64B in, 32B out)
#define V_QUADS (BS * TOTV * NH * 2)      // 696,320
#define Q_QUADS (M_TOT * E / 16)          // 524,288
#define W_QUADS (384 * 256 / 16)          // 6,144
#define CONV_QUADS (V_QUADS + Q_QUADS + W_QUADS)   // 1,226,752
#define CONV_GRID  (CONV_QUADS / 256)     // 4792 exact

// GEMM scratch [32768][384] f32
__device__ float g_scratch[(size_t)M_TOT * NOUT];
// fp16 value cache, transposed: [b][h][pos][32ch]
__device__ __align__(128) __half g_vcache[(size_t)BS * NH * TOTV * 32];
// fp16 copies of Q and W (W rows 0-255 = W_off, 256-383 = W_attn)
__device__ __align__(128) __half g_qh[(size_t)M_TOT * E];
__device__ __align__(128) __half g_wh[(size_t)384 * 256];

// ---------------------------------------------------------------------------
// helpers
// ---------------------------------------------------------------------------
__device__ __forceinline__ void mma_f16(float c[4], const unsigned a[4],
                                        unsigned b0, unsigned b1) {
    asm volatile(
        "mma.sync.aligned.m16n8k16.row.col.f32.f16.f16.f32 "
        "{%0,%1,%2,%3}, {%4,%5,%6,%7}, {%8,%9}, {%0,%1,%2,%3};"
        : "+f"(c[0]), "+f"(c[1]), "+f"(c[2]), "+f"(c[3])
        : "r"(a[0]), "r"(a[1]), "r"(a[2]), "r"(a[3]), "r"(b0), "r"(b1));
}

__device__ __forceinline__ void cp16(void* smem, const void* gmem) {
    unsigned s = (unsigned)__cvta_generic_to_shared(smem);
    asm volatile("cp.async.ca.shared.global [%0], [%1], 16;\n"
                 :: "r"(s), "l"(gmem));
}
#define CP_COMMIT() asm volatile("cp.async.commit_group;\n")
#define CP_WAIT(n)  asm volatile("cp.async.wait_group %0;\n" :: "n"(n))

__device__ __forceinline__ unsigned f2_to_h2(float a, float b) {
    __half2 h = __floats2half2_rn(a, b);
    return *(const unsigned*)&h;
}

// ---------------------------------------------------------------------------
// Convert kernel: value -> transposed fp16 cache; Q -> fp16; W -> fp16.
// Each thread: 4 consecutive float4 (64B in, 32B out). grid = 4792 x 256.
// ---------------------------------------------------------------------------
__global__ __launch_bounds__(256) void convert_kernel(
    const float* __restrict__ value,
    const float* __restrict__ Q,
    const float* __restrict__ Woff,
    const float* __restrict__ Wattn)
{
    int T = blockIdx.x * 256 + threadIdx.x;
    float4 v[4];
    uint4* dst;
    if (T < V_QUADS) {
        int c4b = (4 * T) & 7;            // {0,4}
        int h   = (T >> 1) & 7;
        int pb  = T >> 4;                 // b*TOTV + pos
        int b   = (pb >= TOTV) ? 1 : 0;
        int pos = pb - b * TOTV;
        const float4* src = (const float4*)(value
            + ((size_t)pb * 8 + h) * 32 + c4b * 4);
#pragma unroll
        for (int j = 0; j < 4; j++) v[j] = src[j];
        dst = (uint4*)((uint2*)g_vcache
            + ((size_t)(b * 8 + h) * TOTV + pos) * 8 + c4b);
    } else if (T < V_QUADS + Q_QUADS) {
        int i = T - V_QUADS;
        const float4* src = (const float4*)Q + 4 * i;
#pragma unroll
        for (int j = 0; j < 4; j++) v[j] = src[j];
        dst = (uint4*)g_qh + 2 * i;
    } else {
        int i = T - V_QUADS - Q_QUADS;    // 0..6143
        const float4* src = (i < 4096) ? ((const float4*)Woff + 4 * i)
                                       : ((const float4*)Wattn + 4 * (i - 4096));
#pragma unroll
        for (int j = 0; j < 4; j++) v[j] = src[j];
        dst = (uint4*)g_wh + 2 * i;
    }
    uint4 o0, o1;
    o0.x = f2_to_h2(v[0].x, v[0].y); o0.y = f2_to_h2(v[0].z, v[0].w);
    o0.z = f2_to_h2(v[1].x, v[1].y); o0.w = f2_to_h2(v[1].z, v[1].w);
    o1.x = f2_to_h2(v[2].x, v[2].y); o1.y = f2_to_h2(v[2].z, v[2].w);
    o1.z = f2_to_h2(v[3].x, v[3].y); o1.w = f2_to_h2(v[3].z, v[3].w);
    dst[0] = o0;
    dst[1] = o1;
}

// ---------------------------------------------------------------------------
// GEMM (single-sync double buffer): C[m,n] = sum_k Qh[m,k]*Wh[n,k] + bias[n].
// BM=BN=128, BK=32; 8 warps (4m x 2n). grid = (256, 3).
// ---------------------------------------------------------------------------
__global__ __launch_bounds__(256) void gemm_kernel(
    const float* __restrict__ boff,
    const float* __restrict__ battn)
{
    __shared__ __half As[2][128][40];
    __shared__ __half Bs[2][128][40];

    const int tid  = threadIdx.x;
    const int m0   = blockIdx.x * 128;
    const int n0   = blockIdx.y * 128;
    const int warp = tid >> 5, lane = tid & 31;
    const int wm   = (warp & 3) * 32;
    const int wn   = (warp >> 2) * 64;
    const int g    = lane >> 2;
    const int tg   = lane & 3;

    const int r0 = tid >> 2, c0 = (tid & 3) * 8;
    const int r1 = (tid + 256) >> 2, c1 = c0;

    float acc[2][8][4];
#pragma unroll
    for (int mi = 0; mi < 2; mi++)
#pragma unroll
        for (int ni = 0; ni < 8; ni++)
#pragma unroll
            for (int k = 0; k < 4; k++) acc[mi][ni][k] = 0.f;

    const __half* Abase = g_qh + (size_t)m0 * 256;
    const __half* Bbase = g_wh + (size_t)n0 * 256;

    cp16(&As[0][r0][c0], Abase + r0 * 256 + c0);
    cp16(&As[0][r1][c1], Abase + r1 * 256 + c1);
    cp16(&Bs[0][r0][c0], Bbase + r0 * 256 + c0);
    cp16(&Bs[0][r1][c1], Bbase + r1 * 256 + c1);
    CP_COMMIT();

#pragma unroll
    for (int kt = 0; kt < 8; kt++) {
        CP_WAIT(0);
        __syncthreads();
        if (kt < 7) {
            int s = (kt + 1) & 1, ko = (kt + 1) * 32;
            cp16(&As[s][r0][c0], Abase + r0 * 256 + ko + c0);
            cp16(&As[s][r1][c1], Abase + r1 * 256 + ko + c1);
            cp16(&Bs[s][r0][c0], Bbase + r0 * 256 + ko + c0);
            cp16(&Bs[s][r1][c1], Bbase + r1 * 256 + ko + c1);
            CP_COMMIT();
        }
        const int s = kt & 1;
#pragma unroll
        for (int ks = 0; ks < 32; ks += 16) {
            unsigned a[2][4];
#pragma unroll
            for (int mi = 0; mi < 2; mi++) {
                int r = wm + mi * 16 + g;
                a[mi][0] = *(const unsigned*)(&As[s][r][ks + 2 * tg]);
                a[mi][1] = *(const unsigned*)(&As[s][r + 8][ks + 2 * tg]);
                a[mi][2] = *(const unsigned*)(&As[s][r][ks + 2 * tg + 8]);
                a[mi][3] = *(const unsigned*)(&As[s][r + 8][ks + 2 * tg + 8]);
            }
#pragma unroll
            for (int ni = 0; ni < 8; ni++) {
                unsigned b0 = *(const unsigned*)(&Bs[s][wn + ni * 8 + g][ks + 2 * tg]);
                unsigned b1 = *(const unsigned*)(&Bs[s][wn + ni * 8 + g][ks + 2 * tg + 8]);
                mma_f16(acc[0][ni], a[0], b0, b1);
                mma_f16(acc[1][ni], a[1], b0, b1);
            }
        }
    }

#pragma unroll
    for (int mi = 0; mi < 2; mi++) {
        int row = m0 + wm + mi * 16 + g;
#pragma unroll
        for (int ni = 0; ni < 8; ni++) {
            int col = n0 + wn + ni * 8 + 2 * tg;
            float b0v = (col < 256) ? boff[col] : battn[col - 256];
            float b1v = (col + 1 < 256) ? boff[col + 1] : battn[col + 1 - 256];
            g_scratch[(size_t)row * NOUT + col]           = acc[mi][ni][0] + b0v;
            g_scratch[(size_t)row * NOUT + col + 1]       = acc[mi][ni][1] + b1v;
            g_scratch[(size_t)(row + 8) * NOUT + col]     = acc[mi][ni][2] + b0v;
            g_scratch[(size_t)(row + 8) * NOUT + col + 1] = acc[mi][ni][3] + b1v;
        }
    }
}

// ---------------------------------------------------------------------------
// MSDA kernel: 512-thread blocks (128-reg budget); records hoisted into
// registers BEFORE the gather loop so all 16 LDG.128s are independent with
// register-resident addresses (no LDS in the loop) -> deep load pipelining.
// Block = 16 warps = 32 queries; grid = (NQ/32, NH, BS) = (512, 8, 2).
// ---------------------------------------------------------------------------
__global__ __launch_bounds__(512) void msda_kernel(
    const float* __restrict__ refp,
    float* __restrict__ out)
{
    const int b    = blockIdx.z;
    const int h    = blockIdx.y;
    const int warp = threadIdx.x >> 5;     // 0..15
    const int lane = threadIdx.x & 31;
    const int qh   = lane >> 4;
    const int pt   = lane & 15;
    const int q    = blockIdx.x * 32 + warp * 2 + qh;
    const int qg   = b * NQ + q;

    const float* sc = g_scratch + (size_t)qg * NOUT;

    const int l  = pt >> 2;
    const int p  = pt & 3;
    const int Wl = 128 >> l;
    const int start = (l == 0) ? 0 : (l == 1) ? 16384 : (l == 2) ? 20480 : 21504;

    // ---- softmax over 16 logits (within this half's query) ----
    float lg = sc[256 + h * 16 + pt];
    float mx = lg;
#pragma unroll
    for (int o = 8; o; o >>= 1)
        mx = fmaxf(mx, __shfl_xor_sync(0xffffffffu, mx, o));
    float e = __expf(lg - mx);
    float s = e;
#pragma unroll
    for (int o = 8; o; o >>= 1)
        s += __shfl_xor_sync(0xffffffffu, s, o);
    float w = e / s;

    // ---- tap geometry + folded weights for point pt of this query ----
    float2 of = ((const float2*)(sc + h * 32))[pt];
    float2 rp = ((const float2*)(refp + (size_t)qg * 8))[p];

    float x = rp.x * (float)Wl + of.x - 0.5f;
    float y = rp.y * (float)Wl + of.y - 0.5f;
    float xf = floorf(x), yf = floorf(y);
    float fx = x - xf, fy = y - yf;
    int ix = (int)xf, iy = (int)yf;
    int ixb = min(max(ix, 0), Wl - 2);
    int iyb = min(max(iy, 0), Wl - 2);

    float cw0 = (ixb == ix) ? (1.f - fx) : (ixb == ix + 1) ? fx : 0.f;
    float cw1 = (ixb + 1 == ix) ? (1.f - fx) : (ixb + 1 == ix + 1) ? fx : 0.f;
    float rw0 = (iyb == iy) ? (1.f - fy) : (iyb == iy + 1) ? fy : 0.f;
    float rw1 = (iyb + 1 == iy) ? (1.f - fy) : (iyb + 1 == iy + 1) ? fy : 0.f;

    float wr0 = w * rw0, wr1 = w * rw1;
    unsigned w0 = f2_to_h2(wr0 * cw0, wr0 * cw1);   // row0: (col0, col1)
    unsigned w1 = f2_to_h2(wr1 * cw0, wr1 * cw1);   // row1
    unsigned offA = (unsigned)(start + iyb * Wl + ixb) * 64u;
    unsigned offB = offA + (unsigned)Wl * 64u;

    // ---- smem records: rec[warp][qh][row][pt], stride 17 padding ----
    __shared__ uint2 rec[16][2][2][17];
    {
        uint2 r0; r0.x = offA; r0.y = w0;
        uint2 r1; r1.x = offB; r1.y = w1;
        rec[warp][qh][0][pt] = r0;
        rec[warp][qh][1][pt] = r1;
    }
    __syncwarp();

    // ---- hoist all 16 records into registers (LDS done before the loop) ----
    const int row   = (lane >> 3) & 1;
    const int shamt = ((lane >> 2) & 1) * 16;     // col selects packed weight
    const uint2* recq = &rec[warp][qh][row][0];
    uint2 recs[16];
#pragma unroll
    for (int i = 0; i < 16; i++) recs[i] = recq[i];

    const char* vbase = (const char*)g_vcache
        + (size_t)(b * NH + h) * TOTV * 64 + (lane & 7) * 16;

    float a0 = 0.f, a1 = 0.f, a2 = 0.f, a3 = 0.f;
    float a4 = 0.f, a5 = 0.f, a6 = 0.f, a7 = 0.f;
#pragma unroll
    for (int i = 0; i < 16; i++) {
        uint4 v  = __ldg((const uint4*)(vbase + recs[i].x)); // 8 channels
        float wt = __half2float(
            __ushort_as_half((unsigned short)(recs[i].y >> shamt)));
        float2 f0 = __half22float2(*(const __half2*)&v.x);
        float2 f1 = __half22float2(*(const __half2*)&v.y);
        float2 f2 = __half22float2(*(const __half2*)&v.z);
        float2 f3 = __half22float2(*(const __half2*)&v.w);
        a0 += wt * f0.x; a1 += wt * f0.y;
        a2 += wt * f1.x; a3 += wt * f1.y;
        a4 += wt * f2.x; a5 += wt * f2.y;
        a6 += wt * f3.x; a7 += wt * f3.y;
    }
    // reduce over col (xor 4) then row (xor 8); stays within the half
#pragma unroll
    for (int o = 4; o <= 8; o <<= 1) {
        a0 += __shfl_xor_sync(0xffffffffu, a0, o);
        a1 += __shfl_xor_sync(0xffffffffu, a1, o);
        a2 += __shfl_xor_sync(0xffffffffu, a2, o);
        a3 += __shfl_xor_sync(0xffffffffu, a3, o);
        a4 += __shfl_xor_sync(0xffffffffu, a4, o);
        a5 += __shfl_xor_sync(0xffffffffu, a5, o);
        a6 += __shfl_xor_sync(0xffffffffu, a6, o);
        a7 += __shfl_xor_sync(0xffffffffu, a7, o);
    }

    // ---- smem transpose: sm[channel][q_local], 32 queries per block ----
    __shared__ float sm[32][36];
    if ((lane & 12) == 0) {                 // lanes 0-3 / 16-19
        int ch = (lane & 3) * 8;
        int qc = warp * 2 + qh;
        sm[ch + 0][qc] = a0; sm[ch + 1][qc] = a1;
        sm[ch + 2][qc] = a2; sm[ch + 3][qc] = a3;
        sm[ch + 4][qc] = a4; sm[ch + 5][qc] = a5;
        sm[ch + 6][qc] = a6; sm[ch + 7][qc] = a7;
    }
    __syncthreads();
    // thread t: ch = t>>4 (0..31), q-pair = (t&15)*2 -> 128B per half-warp
    int ch = threadIdx.x >> 4;
    int qi = (threadIdx.x & 15) * 2;
    float2 o2;
    o2.x = sm[ch][qi];
    o2.y = sm[ch][qi + 1];
    *(float2*)(out + ((size_t)(b * 256 + h * 32 + ch)) * NQ
               + blockIdx.x * 32 + qi) = o2;
}

// ---------------------------------------------------------------------------
// Launch
// ---------------------------------------------------------------------------
extern "C" void kernel_launch(void* const* d_in, const int* in_sizes, int n_in,
                              void* d_out, int out_size) {
    const float* query = (const float*)d_in[0];
    const float* value = (const float*)d_in[1];
    const float* refp  = (const float*)d_in[2];
    const float* Woff  = (const float*)d_in[3];
    const float* boff  = (const float*)d_in[4];
    const float* Wattn = (const float*)d_in[5];
    const float* battn = (const float*)d_in[6];
    float* out = (float*)d_out;

    convert_kernel<<<CONV_GRID, 256>>>(value, query, Woff, Wattn);

    dim3 ggrid(M_TOT / 128, 3);
    gemm_kernel<<<ggrid, 256>>>(boff, battn);

    dim3 mgrid(NQ / 32, NH, BS);
    msda_kernel<<<mgrid, 512>>>(refp, out);
}

// round 14
// speedup vs baseline: 1.0413x; 1.0413x over previous
#include <cuda_runtime.h>
#include <cuda_fp16.h>
#include <cstdint>
#include <math.h>

// ---------------------------------------------------------------------------
// Problem constants
// ---------------------------------------------------------------------------
#define BS   2
#define NQ   16384
#define E    256
#define NH   8
#define NL   4
#define NP   4
#define TOTV 21760
#define NOUT 384
#define M_TOT (BS * NQ)

// convert quads (each thread processes 4 float4 = 64B in, 32B out)
#define V_QUADS (BS * TOTV * NH * 2)      // 696,320
#define Q_QUADS (M_TOT * E / 16)          // 524,288
#define W_QUADS (384 * 256 / 16)          // 6,144
#define CONV_QUADS (V_QUADS + Q_QUADS + W_QUADS)   // 1,226,752
#define CONV_GRID  (CONV_QUADS / 256)     // 4792 exact

// GEMM scratch [32768][384] f32
__device__ float g_scratch[(size_t)M_TOT * NOUT];
// fp16 value cache, transposed: [b][h][pos][32ch]
__device__ __align__(128) __half g_vcache[(size_t)BS * NH * TOTV * 32];
// fp16 copies of Q and W (W rows 0-255 = W_off, 256-383 = W_attn)
__device__ __align__(128) __half g_qh[(size_t)M_TOT * E];
__device__ __align__(128) __half g_wh[(size_t)384 * 256];

// ---------------------------------------------------------------------------
// helpers
// ---------------------------------------------------------------------------
__device__ __forceinline__ void mma_f16(float c[4], const unsigned a[4],
                                        unsigned b0, unsigned b1) {
    asm volatile(
        "mma.sync.aligned.m16n8k16.row.col.f32.f16.f16.f32 "
        "{%0,%1,%2,%3}, {%4,%5,%6,%7}, {%8,%9}, {%0,%1,%2,%3};"
        : "+f"(c[0]), "+f"(c[1]), "+f"(c[2]), "+f"(c[3])
        : "r"(a[0]), "r"(a[1]), "r"(a[2]), "r"(a[3]), "r"(b0), "r"(b1));
}

__device__ __forceinline__ void cp16(void* smem, const void* gmem) {
    unsigned s = (unsigned)__cvta_generic_to_shared(smem);
    asm volatile("cp.async.ca.shared.global [%0], [%1], 16;\n"
                 :: "r"(s), "l"(gmem));
}
#define CP_COMMIT() asm volatile("cp.async.commit_group;\n")
#define CP_WAIT(n)  asm volatile("cp.async.wait_group %0;\n" :: "n"(n))

__device__ __forceinline__ unsigned f2_to_h2(float a, float b) {
    __half2 h = __floats2half2_rn(a, b);
    return *(const unsigned*)&h;
}

// ---------------------------------------------------------------------------
// Convert kernel: value -> transposed fp16 cache; Q -> fp16; W -> fp16.
// Each thread: 4 consecutive float4 (64B in, 32B out). grid = 4792 x 256.
// ---------------------------------------------------------------------------
__global__ __launch_bounds__(256) void convert_kernel(
    const float* __restrict__ value,
    const float* __restrict__ Q,
    const float* __restrict__ Woff,
    const float* __restrict__ Wattn)
{
    int T = blockIdx.x * 256 + threadIdx.x;
    float4 v[4];
    uint4* dst;
    if (T < V_QUADS) {
        int c4b = (4 * T) & 7;            // {0,4}
        int h   = (T >> 1) & 7;
        int pb  = T >> 4;                 // b*TOTV + pos
        int b   = (pb >= TOTV) ? 1 : 0;
        int pos = pb - b * TOTV;
        const float4* src = (const float4*)(value
            + ((size_t)pb * 8 + h) * 32 + c4b * 4);
#pragma unroll
        for (int j = 0; j < 4; j++) v[j] = src[j];
        dst = (uint4*)((uint2*)g_vcache
            + ((size_t)(b * 8 + h) * TOTV + pos) * 8 + c4b);
    } else if (T < V_QUADS + Q_QUADS) {
        int i = T - V_QUADS;
        const float4* src = (const float4*)Q + 4 * i;
#pragma unroll
        for (int j = 0; j < 4; j++) v[j] = src[j];
        dst = (uint4*)g_qh + 2 * i;
    } else {
        int i = T - V_QUADS - Q_QUADS;    // 0..6143
        const float4* src = (i < 4096) ? ((const float4*)Woff + 4 * i)
                                       : ((const float4*)Wattn + 4 * (i - 4096));
#pragma unroll
        for (int j = 0; j < 4; j++) v[j] = src[j];
        dst = (uint4*)g_wh + 2 * i;
    }
    uint4 o0, o1;
    o0.x = f2_to_h2(v[0].x, v[0].y); o0.y = f2_to_h2(v[0].z, v[0].w);
    o0.z = f2_to_h2(v[1].x, v[1].y); o0.w = f2_to_h2(v[1].z, v[1].w);
    o1.x = f2_to_h2(v[2].x, v[2].y); o1.y = f2_to_h2(v[2].z, v[2].w);
    o1.z = f2_to_h2(v[3].x, v[3].y); o1.w = f2_to_h2(v[3].z, v[3].w);
    dst[0] = o0;
    dst[1] = o1;
}

// ---------------------------------------------------------------------------
// GEMM: C[m,n] = sum_k Qh[m,k]*Wh[n,k] + bias[n], fp16 in, f32 accum.
// BM=BN=128, BK=32; cp.async double buffer, one sync per k-tile.
// NEW: smem-staged COALESCED epilogue — accumulators are deposited (with
// bias) into a 64x132 f32 smem buffer (aliasing the dead As/Bs), then
// stored as contiguous 512B row segments (float4), removing the ~4x store
// sector amplification of the old scattered 8B stores.
// 8 warps (4m x 2n). grid = (256, 3).
// ---------------------------------------------------------------------------
__global__ __launch_bounds__(256) void gemm_kernel(
    const float* __restrict__ boff,
    const float* __restrict__ battn)
{
    __shared__ __align__(16) char sraw[40960];
    typedef __half HalfTile[128][40];
    HalfTile* As = reinterpret_cast<HalfTile*>(sraw);            // As[2]
    HalfTile* Bs = reinterpret_cast<HalfTile*>(sraw + 20480);    // Bs[2]
    float (*eb)[132] = reinterpret_cast<float(*)[132]>(sraw);    // 64x132

    const int tid  = threadIdx.x;
    const int m0   = blockIdx.x * 128;
    const int n0   = blockIdx.y * 128;
    const int warp = tid >> 5, lane = tid & 31;
    const int wm   = (warp & 3) * 32;
    const int wn   = (warp >> 2) * 64;
    const int g    = lane >> 2;
    const int tg   = lane & 3;

    const int r0 = tid >> 2, c0 = (tid & 3) * 8;
    const int r1 = (tid + 256) >> 2, c1 = c0;

    float acc[2][8][4];
#pragma unroll
    for (int mi = 0; mi < 2; mi++)
#pragma unroll
        for (int ni = 0; ni < 8; ni++)
#pragma unroll
            for (int k = 0; k < 4; k++) acc[mi][ni][k] = 0.f;

    const __half* Abase = g_qh + (size_t)m0 * 256;
    const __half* Bbase = g_wh + (size_t)n0 * 256;

    cp16(&As[0][r0][c0], Abase + r0 * 256 + c0);
    cp16(&As[0][r1][c1], Abase + r1 * 256 + c1);
    cp16(&Bs[0][r0][c0], Bbase + r0 * 256 + c0);
    cp16(&Bs[0][r1][c1], Bbase + r1 * 256 + c1);
    CP_COMMIT();

#pragma unroll
    for (int kt = 0; kt < 8; kt++) {
        CP_WAIT(0);
        __syncthreads();
        if (kt < 7) {
            int s = (kt + 1) & 1, ko = (kt + 1) * 32;
            cp16(&As[s][r0][c0], Abase + r0 * 256 + ko + c0);
            cp16(&As[s][r1][c1], Abase + r1 * 256 + ko + c1);
            cp16(&Bs[s][r0][c0], Bbase + r0 * 256 + ko + c0);
            cp16(&Bs[s][r1][c1], Bbase + r1 * 256 + ko + c1);
            CP_COMMIT();
        }
        const int s = kt & 1;
#pragma unroll
        for (int ks = 0; ks < 32; ks += 16) {
            unsigned a[2][4];
#pragma unroll
            for (int mi = 0; mi < 2; mi++) {
                int r = wm + mi * 16 + g;
                a[mi][0] = *(const unsigned*)(&As[s][r][ks + 2 * tg]);
                a[mi][1] = *(const unsigned*)(&As[s][r + 8][ks + 2 * tg]);
                a[mi][2] = *(const unsigned*)(&As[s][r][ks + 2 * tg + 8]);
                a[mi][3] = *(const unsigned*)(&As[s][r + 8][ks + 2 * tg + 8]);
            }
#pragma unroll
            for (int ni = 0; ni < 8; ni++) {
                unsigned b0 = *(const unsigned*)(&Bs[s][wn + ni * 8 + g][ks + 2 * tg]);
                unsigned b1 = *(const unsigned*)(&Bs[s][wn + ni * 8 + g][ks + 2 * tg + 8]);
                mma_f16(acc[0][ni], a[0], b0, b1);
                mma_f16(acc[1][ni], a[1], b0, b1);
            }
        }
    }

    // ---- coalesced epilogue: two 64-row chunks through smem ----
#pragma unroll
    for (int half = 0; half < 2; half++) {
        const int rbase = half * 64;
        __syncthreads();                       // As/Bs reads done / prev chunk stored
        if ((wm & 64) == rbase) {              // warps owning rows of this chunk
#pragma unroll
            for (int mi = 0; mi < 2; mi++) {
                int r = (wm & 32) + mi * 16 + g;   // row within chunk
#pragma unroll
                for (int ni = 0; ni < 8; ni++) {
                    int col  = wn + ni * 8 + 2 * tg;
                    int gcol = n0 + col;
                    float b0v = (gcol < 256) ? boff[gcol] : battn[gcol - 256];
                    float b1v = (gcol + 1 < 256) ? boff[gcol + 1]
                                                 : battn[gcol + 1 - 256];
                    eb[r][col]         = acc[mi][ni][0] + b0v;
                    eb[r][col + 1]     = acc[mi][ni][1] + b1v;
                    eb[r + 8][col]     = acc[mi][ni][2] + b0v;
                    eb[r + 8][col + 1] = acc[mi][ni][3] + b1v;
                }
            }
        }
        __syncthreads();
        // 64 rows x 128 cols -> contiguous 512B row segments
#pragma unroll
        for (int i = 0; i < 8; i++) {
            int idx = tid + i * 256;           // 0..2047
            int r = idx >> 5;                  // 0..63
            int c = (idx & 31) * 4;            // 0..124
            float4 v = *(const float4*)(&eb[r][c]);
            *(float4*)(g_scratch + (size_t)(m0 + rbase + r) * NOUT + n0 + c) = v;
        }
    }
}

// ---------------------------------------------------------------------------
// MSDA kernel (R12 version — empirically fastest): 2 queries per warp,
// 512-thread blocks (128-reg budget). Gather loop: LDS.64 record + LDG.128
// + 8 FFMA per iter. grid = (NQ/32, NH, BS) = (512, 8, 2).
// ---------------------------------------------------------------------------
__global__ __launch_bounds__(512) void msda_kernel(
    const float* __restrict__ refp,
    float* __restrict__ out)
{
    const int b    = blockIdx.z;
    const int h    = blockIdx.y;
    const int warp = threadIdx.x >> 5;     // 0..15
    const int lane = threadIdx.x & 31;
    const int qh   = lane >> 4;
    const int pt   = lane & 15;
    const int q    = blockIdx.x * 32 + warp * 2 + qh;
    const int qg   = b * NQ + q;

    const float* sc = g_scratch + (size_t)qg * NOUT;

    const int l  = pt >> 2;
    const int p  = pt & 3;
    const int Wl = 128 >> l;
    const int start = (l == 0) ? 0 : (l == 1) ? 16384 : (l == 2) ? 20480 : 21504;

    // ---- softmax over 16 logits (within this half's query) ----
    float lg = sc[256 + h * 16 + pt];
    float mx = lg;
#pragma unroll
    for (int o = 8; o; o >>= 1)
        mx = fmaxf(mx, __shfl_xor_sync(0xffffffffu, mx, o));
    float e = __expf(lg - mx);
    float s = e;
#pragma unroll
    for (int o = 8; o; o >>= 1)
        s += __shfl_xor_sync(0xffffffffu, s, o);
    float w = e / s;

    // ---- tap geometry + folded weights for point pt of this query ----
    float2 of = ((const float2*)(sc + h * 32))[pt];
    float2 rp = ((const float2*)(refp + (size_t)qg * 8))[p];

    float x = rp.x * (float)Wl + of.x - 0.5f;
    float y = rp.y * (float)Wl + of.y - 0.5f;
    float xf = floorf(x), yf = floorf(y);
    float fx = x - xf, fy = y - yf;
    int ix = (int)xf, iy = (int)yf;
    int ixb = min(max(ix, 0), Wl - 2);
    int iyb = min(max(iy, 0), Wl - 2);

    float cw0 = (ixb == ix) ? (1.f - fx) : (ixb == ix + 1) ? fx : 0.f;
    float cw1 = (ixb + 1 == ix) ? (1.f - fx) : (ixb + 1 == ix + 1) ? fx : 0.f;
    float rw0 = (iyb == iy) ? (1.f - fy) : (iyb == iy + 1) ? fy : 0.f;
    float rw1 = (iyb + 1 == iy) ? (1.f - fy) : (iyb + 1 == iy + 1) ? fy : 0.f;

    float wr0 = w * rw0, wr1 = w * rw1;
    unsigned w0 = f2_to_h2(wr0 * cw0, wr0 * cw1);   // row0: (col0, col1)
    unsigned w1 = f2_to_h2(wr1 * cw0, wr1 * cw1);   // row1
    unsigned offA = (unsigned)(start + iyb * Wl + ixb) * 64u;
    unsigned offB = offA + (unsigned)Wl * 64u;

    // ---- smem records: rec[warp][qh][row][pt], stride 17 padding ----
    __shared__ uint2 rec[16][2][2][17];
    {
        uint2 r0; r0.x = offA; r0.y = w0;
        uint2 r1; r1.x = offB; r1.y = w1;
        rec[warp][qh][0][pt] = r0;
        rec[warp][qh][1][pt] = r1;
    }
    __syncwarp();

    // ---- gather loop ----
    const int row   = (lane >> 3) & 1;
    const int shamt = ((lane >> 2) & 1) * 16;     // col selects packed weight
    const uint2* recq = &rec[warp][qh][row][0];
    const char* vbase = (const char*)g_vcache
        + (size_t)(b * NH + h) * TOTV * 64 + (lane & 7) * 16;

    float a0 = 0.f, a1 = 0.f, a2 = 0.f, a3 = 0.f;
    float a4 = 0.f, a5 = 0.f, a6 = 0.f, a7 = 0.f;
#pragma unroll
    for (int i = 0; i < 16; i++) {
        uint2 ei = recq[i];                             // LDS.64 broadcast x4
        uint4 v  = __ldg((const uint4*)(vbase + ei.x)); // 8 channels
        float wt = __half2float(
            __ushort_as_half((unsigned short)(ei.y >> shamt)));
        float2 f0 = __half22float2(*(const __half2*)&v.x);
        float2 f1 = __half22float2(*(const __half2*)&v.y);
        float2 f2 = __half22float2(*(const __half2*)&v.z);
        float2 f3 = __half22float2(*(const __half2*)&v.w);
        a0 += wt * f0.x; a1 += wt * f0.y;
        a2 += wt * f1.x; a3 += wt * f1.y;
        a4 += wt * f2.x; a5 += wt * f2.y;
        a6 += wt * f3.x; a7 += wt * f3.y;
    }
    // reduce over col (xor 4) then row (xor 8); stays within the half
#pragma unroll
    for (int o = 4; o <= 8; o <<= 1) {
        a0 += __shfl_xor_sync(0xffffffffu, a0, o);
        a1 += __shfl_xor_sync(0xffffffffu, a1, o);
        a2 += __shfl_xor_sync(0xffffffffu, a2, o);
        a3 += __shfl_xor_sync(0xffffffffu, a3, o);
        a4 += __shfl_xor_sync(0xffffffffu, a4, o);
        a5 += __shfl_xor_sync(0xffffffffu, a5, o);
        a6 += __shfl_xor_sync(0xffffffffu, a6, o);
        a7 += __shfl_xor_sync(0xffffffffu, a7, o);
    }

    // ---- smem transpose: sm[channel][q_local], 32 queries per block ----
    __shared__ float sm[32][36];
    if ((lane & 12) == 0) {                 // lanes 0-3 / 16-19
        int ch = (lane & 3) * 8;
        int qc = warp * 2 + qh;
        sm[ch + 0][qc] = a0; sm[ch + 1][qc] = a1;
        sm[ch + 2][qc] = a2; sm[ch + 3][qc] = a3;
        sm[ch + 4][qc] = a4; sm[ch + 5][qc] = a5;
        sm[ch + 6][qc] = a6; sm[ch + 7][qc] = a7;
    }
    __syncthreads();
    // thread t: ch = t>>4 (0..31), q-pair = (t&15)*2 -> 128B per half-warp
    int ch = threadIdx.x >> 4;
    int qi = (threadIdx.x & 15) * 2;
    float2 o2;
    o2.x = sm[ch][qi];
    o2.y = sm[ch][qi + 1];
    *(float2*)(out + ((size_t)(b * 256 + h * 32 + ch)) * NQ
               + blockIdx.x * 32 + qi) = o2;
}

// ---------------------------------------------------------------------------
// Launch
// ---------------------------------------------------------------------------
extern "C" void kernel_launch(void* const* d_in, const int* in_sizes, int n_in,
                              void* d_out, int out_size) {
    const float* query = (const float*)d_in[0];
    const float* value = (const float*)d_in[1];
    const float* refp  = (const float*)d_in[2];
    const float* Woff  = (const float*)d_in[3];
    const float* boff  = (const float*)d_in[4];
    const float* Wattn = (const float*)d_in[5];
    const float* battn = (const float*)d_in[6];
    float* out = (float*)d_out;

    convert_kernel<<<CONV_GRID, 256>>>(value, query, Woff, Wattn);

    dim3 ggrid(M_TOT / 128, 3);
    gemm_kernel<<<ggrid, 256>>>(boff, battn);

    dim3 mgrid(NQ / 32, NH, BS);
    msda_kernel<<<mgrid, 512>>>(refp, out);
}

// round 15
// speedup vs baseline: 1.0592x; 1.0172x over previous
#include <cuda_runtime.h>
#include <cuda_fp16.h>
#include <cstdint>
#include <math.h>

// ---------------------------------------------------------------------------
// Problem constants
// ---------------------------------------------------------------------------
#define BS   2
#define NQ   16384
#define E    256
#define NH   4096 / 512   // 8 (kept literal below; defined for clarity)
#undef  NH
#define NH   8
#define NL   4
#define NP   4
#define TOTV 21760
#define NOUT 384
#define M_TOT (BS * NQ)

// convert quads (64B in, 32B out each); each thread does TWO far-apart quads
#define V_QUADS (BS * TOTV * NH * 2)      // 696,320
#define Q_QUADS (M_TOT * E / 16)          // 524,288
#define W_QUADS (384 * 256 / 16)          // 6,144
#define CONV_QUADS (V_QUADS + Q_QUADS + W_QUADS)   // 1,226,752
#define CONV_HALF  (CONV_QUADS / 2)       // 613,376
#define CONV_GRID  (CONV_HALF / 256)      // 2396 exact

#define GEMM_SMEM  61440                  // 3 stages x 20KB

// GEMM scratch [32768][384] f32
__device__ float g_scratch[(size_t)M_TOT * NOUT];
// fp16 value cache, transposed: [b][h][pos][32ch]
__device__ __align__(128) __half g_vcache[(size_t)BS * NH * TOTV * 32];
// fp16 copies of Q and W (W rows 0-255 = W_off, 256-383 = W_attn)
__device__ __align__(128) __half g_qh[(size_t)M_TOT * E];
__device__ __align__(128) __half g_wh[(size_t)384 * 256];

// ---------------------------------------------------------------------------
// helpers
// ---------------------------------------------------------------------------
__device__ __forceinline__ void mma_f16(float c[4], const unsigned a[4],
                                        unsigned b0, unsigned b1) {
    asm volatile(
        "mma.sync.aligned.m16n8k16.row.col.f32.f16.f16.f32 "
        "{%0,%1,%2,%3}, {%4,%5,%6,%7}, {%8,%9}, {%0,%1,%2,%3};"
        : "+f"(c[0]), "+f"(c[1]), "+f"(c[2]), "+f"(c[3])
        : "r"(a[0]), "r"(a[1]), "r"(a[2]), "r"(a[3]), "r"(b0), "r"(b1));
}

__device__ __forceinline__ void cp16(void* smem, const void* gmem) {
    unsigned s = (unsigned)__cvta_generic_to_shared(smem);
    asm volatile("cp.async.ca.shared.global [%0], [%1], 16;\n"
                 :: "r"(s), "l"(gmem));
}
#define CP_COMMIT() asm volatile("cp.async.commit_group;\n")
#define CP_WAIT(n)  asm volatile("cp.async.wait_group %0;\n" :: "n"(n))

__device__ __forceinline__ unsigned f2_to_h2(float a, float b) {
    __half2 h = __floats2half2_rn(a, b);
    return *(const unsigned*)&h;
}

// ---------------------------------------------------------------------------
// Convert kernel: value -> transposed fp16 cache; Q -> fp16; W -> fp16.
// Each thread handles TWO 4-float4 items, CONV_HALF apart (MLP=8 while
// keeping the 64B-contiguous-per-thread layout). grid = 2396 x 256.
// ---------------------------------------------------------------------------
__global__ __launch_bounds__(256) void convert_kernel(
    const float* __restrict__ value,
    const float* __restrict__ Q,
    const float* __restrict__ Woff,
    const float* __restrict__ Wattn)
{
    int T0 = blockIdx.x * 256 + threadIdx.x;
#pragma unroll
    for (int half = 0; half < 2; half++) {
        int T = T0 + half * CONV_HALF;
        float4 v[4];
        uint4* dst;
        if (T < V_QUADS) {
            int c4b = (4 * T) & 7;            // {0,4}
            int h   = (T >> 1) & 7;
            int pb  = T >> 4;                 // b*TOTV + pos
            int b   = (pb >= TOTV) ? 1 : 0;
            int pos = pb - b * TOTV;
            const float4* src = (const float4*)(value
                + ((size_t)pb * 8 + h) * 32 + c4b * 4);
#pragma unroll
            for (int j = 0; j < 4; j++) v[j] = src[j];
            dst = (uint4*)((uint2*)g_vcache
                + ((size_t)(b * 8 + h) * TOTV + pos) * 8 + c4b);
        } else if (T < V_QUADS + Q_QUADS) {
            int i = T - V_QUADS;
            const float4* src = (const float4*)Q + 4 * i;
#pragma unroll
            for (int j = 0; j < 4; j++) v[j] = src[j];
            dst = (uint4*)g_qh + 2 * i;
        } else {
            int i = T - V_QUADS - Q_QUADS;    // 0..6143
            const float4* src = (i < 4096) ? ((const float4*)Woff + 4 * i)
                                           : ((const float4*)Wattn + 4 * (i - 4096));
#pragma unroll
            for (int j = 0; j < 4; j++) v[j] = src[j];
            dst = (uint4*)g_wh + 2 * i;
        }
        uint4 o0, o1;
        o0.x = f2_to_h2(v[0].x, v[0].y); o0.y = f2_to_h2(v[0].z, v[0].w);
        o0.z = f2_to_h2(v[1].x, v[1].y); o0.w = f2_to_h2(v[1].z, v[1].w);
        o1.x = f2_to_h2(v[2].x, v[2].y); o1.y = f2_to_h2(v[2].z, v[2].w);
        o1.z = f2_to_h2(v[3].x, v[3].y); o1.w = f2_to_h2(v[3].z, v[3].w);
        dst[0] = o0;
        dst[1] = o1;
    }
}

// ---------------------------------------------------------------------------
// GEMM: C[m,n] = sum_k Qh[m,k]*Wh[n,k] + bias[n], fp16 in, f32 accum.
// BM=BN=128, BK=32; cp.async 3-STAGE pipeline (two tile-loads in flight
// behind each compute). Dynamic smem 60KB (attribute set in static init).
// Coalesced smem-staged epilogue. 8 warps (4m x 2n). grid = (256, 3).
// ---------------------------------------------------------------------------
__global__ __launch_bounds__(256) void gemm_kernel(
    const float* __restrict__ boff,
    const float* __restrict__ battn)
{
    extern __shared__ __align__(16) char sraw[];
    // stage i: As at i*20480, Bs at i*20480 + 10240 (each 128x40 half)
    float (*eb)[132] = reinterpret_cast<float(*)[132]>(sraw);    // 64x132 alias

    const int tid  = threadIdx.x;
    const int m0   = blockIdx.x * 128;
    const int n0   = blockIdx.y * 128;
    const int warp = tid >> 5, lane = tid & 31;
    const int wm   = (warp & 3) * 32;
    const int wn   = (warp >> 2) * 64;
    const int g    = lane >> 2;
    const int tg   = lane & 3;

    const int r0 = tid >> 2, c0 = (tid & 3) * 8;
    const int r1 = (tid + 256) >> 2, c1 = c0;

    float acc[2][8][4];
#pragma unroll
    for (int mi = 0; mi < 2; mi++)
#pragma unroll
        for (int ni = 0; ni < 8; ni++)
#pragma unroll
            for (int k = 0; k < 4; k++) acc[mi][ni][k] = 0.f;

    const __half* Abase = g_qh + (size_t)m0 * 256;
    const __half* Bbase = g_wh + (size_t)n0 * 256;

    // prologue: stages 0 and 1
#pragma unroll
    for (int pk = 0; pk < 2; pk++) {
        __half (*Asb)[40] = (__half(*)[40])(sraw + pk * 20480);
        __half (*Bsb)[40] = (__half(*)[40])(sraw + pk * 20480 + 10240);
        int ko = pk * 32;
        cp16(&Asb[r0][c0], Abase + r0 * 256 + ko + c0);
        cp16(&Asb[r1][c1], Abase + r1 * 256 + ko + c1);
        cp16(&Bsb[r0][c0], Bbase + r0 * 256 + ko + c0);
        cp16(&Bsb[r1][c1], Bbase + r1 * 256 + ko + c1);
        CP_COMMIT();
    }

#pragma unroll
    for (int kt = 0; kt < 8; kt++) {
        if (kt < 7) { CP_WAIT(1); } else { CP_WAIT(0); }
        __syncthreads();
        if (kt < 6) {
            int st = (kt + 2) % 3, ko = (kt + 2) * 32;
            __half (*Asb)[40] = (__half(*)[40])(sraw + st * 20480);
            __half (*Bsb)[40] = (__half(*)[40])(sraw + st * 20480 + 10240);
            cp16(&Asb[r0][c0], Abase + r0 * 256 + ko + c0);
            cp16(&Asb[r1][c1], Abase + r1 * 256 + ko + c1);
            cp16(&Bsb[r0][c0], Bbase + r0 * 256 + ko + c0);
            cp16(&Bsb[r1][c1], Bbase + r1 * 256 + ko + c1);
            CP_COMMIT();
        }
        const int s = kt % 3;
        __half (*As)[40] = (__half(*)[40])(sraw + s * 20480);
        __half (*Bs)[40] = (__half(*)[40])(sraw + s * 20480 + 10240);
#pragma unroll
        for (int ks = 0; ks < 32; ks += 16) {
            unsigned a[2][4];
#pragma unroll
            for (int mi = 0; mi < 2; mi++) {
                int r = wm + mi * 16 + g;
                a[mi][0] = *(const unsigned*)(&As[r][ks + 2 * tg]);
                a[mi][1] = *(const unsigned*)(&As[r + 8][ks + 2 * tg]);
                a[mi][2] = *(const unsigned*)(&As[r][ks + 2 * tg + 8]);
                a[mi][3] = *(const unsigned*)(&As[r + 8][ks + 2 * tg + 8]);
            }
#pragma unroll
            for (int ni = 0; ni < 8; ni++) {
                unsigned b0 = *(const unsigned*)(&Bs[wn + ni * 8 + g][ks + 2 * tg]);
                unsigned b1 = *(const unsigned*)(&Bs[wn + ni * 8 + g][ks + 2 * tg + 8]);
                mma_f16(acc[0][ni], a[0], b0, b1);
                mma_f16(acc[1][ni], a[1], b0, b1);
            }
        }
    }

    // ---- coalesced epilogue: two 64-row chunks through smem ----
#pragma unroll
    for (int half = 0; half < 2; half++) {
        const int rbase = half * 64;
        __syncthreads();
        if ((wm & 64) == rbase) {
#pragma unroll
            for (int mi = 0; mi < 2; mi++) {
                int r = (wm & 32) + mi * 16 + g;
#pragma unroll
                for (int ni = 0; ni < 8; ni++) {
                    int col  = wn + ni * 8 + 2 * tg;
                    int gcol = n0 + col;
                    float b0v = (gcol < 256) ? boff[gcol] : battn[gcol - 256];
                    float b1v = (gcol + 1 < 256) ? boff[gcol + 1]
                                                 : battn[gcol + 1 - 256];
                    eb[r][col]         = acc[mi][ni][0] + b0v;
                    eb[r][col + 1]     = acc[mi][ni][1] + b1v;
                    eb[r + 8][col]     = acc[mi][ni][2] + b0v;
                    eb[r + 8][col + 1] = acc[mi][ni][3] + b1v;
                }
            }
        }
        __syncthreads();
#pragma unroll
        for (int i = 0; i < 8; i++) {
            int idx = tid + i * 256;
            int r = idx >> 5;
            int c = (idx & 31) * 4;
            float4 v = *(const float4*)(&eb[r][c]);
            *(float4*)(g_scratch + (size_t)(m0 + rbase + r) * NOUT + n0 + c) = v;
        }
    }
}

// one-time: allow 60KB dynamic smem on gemm_kernel
namespace {
struct _AthenaInit {
    _AthenaInit() {
        cudaFuncSetAttribute(gemm_kernel,
                             cudaFuncAttributeMaxDynamicSharedMemorySize,
                             GEMM_SMEM);
    }
};
_AthenaInit _athena_init;
}

// ---------------------------------------------------------------------------
// MSDA kernel (R12/R14 version — empirically fastest): 2 queries per warp,
// 512-thread blocks. grid = (NQ/32, NH, BS) = (512, 8, 2).
// ---------------------------------------------------------------------------
__global__ __launch_bounds__(512) void msda_kernel(
    const float* __restrict__ refp,
    float* __restrict__ out)
{
    const int b    = blockIdx.z;
    const int h    = blockIdx.y;
    const int warp = threadIdx.x >> 5;     // 0..15
    const int lane = threadIdx.x & 31;
    const int qh   = lane >> 4;
    const int pt   = lane & 15;
    const int q    = blockIdx.x * 32 + warp * 2 + qh;
    const int qg   = b * NQ + q;

    const float* sc = g_scratch + (size_t)qg * NOUT;

    const int l  = pt >> 2;
    const int p  = pt & 3;
    const int Wl = 128 >> l;
    const int start = (l == 0) ? 0 : (l == 1) ? 16384 : (l == 2) ? 20480 : 21504;

    // ---- softmax over 16 logits (within this half's query) ----
    float lg = sc[256 + h * 16 + pt];
    float mx = lg;
#pragma unroll
    for (int o = 8; o; o >>= 1)
        mx = fmaxf(mx, __shfl_xor_sync(0xffffffffu, mx, o));
    float e = __expf(lg - mx);
    float s = e;
#pragma unroll
    for (int o = 8; o; o >>= 1)
        s += __shfl_xor_sync(0xffffffffu, s, o);
    float w = e / s;

    // ---- tap geometry + folded weights for point pt of this query ----
    float2 of = ((const float2*)(sc + h * 32))[pt];
    float2 rp = ((const float2*)(refp + (size_t)qg * 8))[p];

    float x = rp.x * (float)Wl + of.x - 0.5f;
    float y = rp.y * (float)Wl + of.y - 0.5f;
    float xf = floorf(x), yf = floorf(y);
    float fx = x - xf, fy = y - yf;
    int ix = (int)xf, iy = (int)yf;
    int ixb = min(max(ix, 0), Wl - 2);
    int iyb = min(max(iy, 0), Wl - 2);

    float cw0 = (ixb == ix) ? (1.f - fx) : (ixb == ix + 1) ? fx : 0.f;
    float cw1 = (ixb + 1 == ix) ? (1.f - fx) : (ixb + 1 == ix + 1) ? fx : 0.f;
    float rw0 = (iyb == iy) ? (1.f - fy) : (iyb == iy + 1) ? fy : 0.f;
    float rw1 = (iyb + 1 == iy) ? (1.f - fy) : (iyb + 1 == iy + 1) ? fy : 0.f;

    float wr0 = w * rw0, wr1 = w * rw1;
    unsigned w0 = f2_to_h2(wr0 * cw0, wr0 * cw1);   // row0: (col0, col1)
    unsigned w1 = f2_to_h2(wr1 * cw0, wr1 * cw1);   // row1
    unsigned offA = (unsigned)(start + iyb * Wl + ixb) * 64u;
    unsigned offB = offA + (unsigned)Wl * 64u;

    // ---- smem records: rec[warp][qh][row][pt], stride 17 padding ----
    __shared__ uint2 rec[16][2][2][17];
    {
        uint2 r0; r0.x = offA; r0.y = w0;
        uint2 r1; r1.x = offB; r1.y = w1;
        rec[warp][qh][0][pt] = r0;
        rec[warp][qh][1][pt] = r1;
    }
    __syncwarp();

    // ---- gather loop ----
    const int row   = (lane >> 3) & 1;
    const int shamt = ((lane >> 2) & 1) * 16;     // col selects packed weight
    const uint2* recq = &rec[warp][qh][row][0];
    const char* vbase = (const char*)g_vcache
        + (size_t)(b * NH + h) * TOTV * 64 + (lane & 7) * 16;

    float a0 = 0.f, a1 = 0.f, a2 = 0.f, a3 = 0.f;
    float a4 = 0.f, a5 = 0.f, a6 = 0.f, a7 = 0.f;
#pragma unroll
    for (int i = 0; i < 16; i++) {
        uint2 ei = recq[i];                             // LDS.64 broadcast x4
        uint4 v  = __ldg((const uint4*)(vbase + ei.x)); // 8 channels
        float wt = __half2float(
            __ushort_as_half((unsigned short)(ei.y >> shamt)));
        float2 f0 = __half22float2(*(const __half2*)&v.x);
        float2 f1 = __half22float2(*(const __half2*)&v.y);
        float2 f2 = __half22float2(*(const __half2*)&v.z);
        float2 f3 = __half22float2(*(const __half2*)&v.w);
        a0 += wt * f0.x; a1 += wt * f0.y;
        a2 += wt * f1.x; a3 += wt * f1.y;
        a4 += wt * f2.x; a5 += wt * f2.y;
        a6 += wt * f3.x; a7 += wt * f3.y;
    }
    // reduce over col (xor 4) then row (xor 8); stays within the half
#pragma unroll
    for (int o = 4; o <= 8; o <<= 1) {
        a0 += __shfl_xor_sync(0xffffffffu, a0, o);
        a1 += __shfl_xor_sync(0xffffffffu, a1, o);
        a2 += __shfl_xor_sync(0xffffffffu, a2, o);
        a3 += __shfl_xor_sync(0xffffffffu, a3, o);
        a4 += __shfl_xor_sync(0xffffffffu, a4, o);
        a5 += __shfl_xor_sync(0xffffffffu, a5, o);
        a6 += __shfl_xor_sync(0xffffffffu, a6, o);
        a7 += __shfl_xor_sync(0xffffffffu, a7, o);
    }

    // ---- smem transpose: sm[channel][q_local], 32 queries per block ----
    __shared__ float sm[32][36];
    if ((lane & 12) == 0) {                 // lanes 0-3 / 16-19
        int ch = (lane & 3) * 8;
        int qc = warp * 2 + qh;
        sm[ch + 0][qc] = a0; sm[ch + 1][qc] = a1;
        sm[ch + 2][qc] = a2; sm[ch + 3][qc] = a3;
        sm[ch + 4][qc] = a4; sm[ch + 5][qc] = a5;
        sm[ch + 6][qc] = a6; sm[ch + 7][qc] = a7;
    }
    __syncthreads();
    int ch = threadIdx.x >> 4;
    int qi = (threadIdx.x & 15) * 2;
    float2 o2;
    o2.x = sm[ch][qi];
    o2.y = sm[ch][qi + 1];
    *(float2*)(out + ((size_t)(b * 256 + h * 32 + ch)) * NQ
               + blockIdx.x * 32 + qi) = o2;
}

// ---------------------------------------------------------------------------
// Launch
// ---------------------------------------------------------------------------
extern "C" void kernel_launch(void* const* d_in, const int* in_sizes, int n_in,
                              void* d_out, int out_size) {
    const float* query = (const float*)d_in[0];
    const float* value = (const float*)d_in[1];
    const float* refp  = (const float*)d_in[2];
    const float* Woff  = (const float*)d_in[3];
    const float* boff  = (const float*)d_in[4];
    const float* Wattn = (const float*)d_in[5];
    const float* battn = (const float*)d_in[6];
    float* out = (float*)d_out;

    convert_kernel<<<CONV_GRID, 256>>>(value, query, Woff, Wattn);

    dim3 ggrid(M_TOT / 128, 3);
    gemm_kernel<<<ggrid, 256, GEMM_SMEM>>>(boff, battn);

    dim3 mgrid(NQ / 32, NH, BS);
    msda_kernel<<<mgrid, 512>>>(refp, out);
}

// round 16
// speedup vs baseline: 1.0690x; 1.0093x over previous
#include <cuda_runtime.h>
#include <cuda_fp16.h>
#include <cstdint>
#include <math.h>

// ---------------------------------------------------------------------------
// Problem constants
// ---------------------------------------------------------------------------
#define BS   2
#define NQ   16384
#define E    256
#define NH   8
#define NL   4
#define NP   4
#define TOTV 21760
#define NOUT 384
#define M_TOT (BS * NQ)

// convert quads (each thread processes 4 float4 = 64B in, 32B out)
#define V_QUADS (BS * TOTV * NH * 2)      // 696,320
#define Q_QUADS (M_TOT * E / 16)          // 524,288
#define W_QUADS (384 * 256 / 16)          // 6,144
#define CONV_QUADS (V_QUADS + Q_QUADS + W_QUADS)   // 1,226,752
#define CONV_GRID  (CONV_QUADS / 256)     // 4792 exact

#define GEMM_SMEM  61440                  // 3 stages x 20KB

// GEMM scratch [32768][384] f32
__device__ float g_scratch[(size_t)M_TOT * NOUT];
// fp16 value cache, transposed: [b][h][pos][32ch]
__device__ __align__(128) __half g_vcache[(size_t)BS * NH * TOTV * 32];
// fp16 copies of Q and W (W rows 0-255 = W_off, 256-383 = W_attn)
__device__ __align__(128) __half g_qh[(size_t)M_TOT * E];
__device__ __align__(128) __half g_wh[(size_t)384 * 256];

// ---------------------------------------------------------------------------
// helpers
// ---------------------------------------------------------------------------
__device__ __forceinline__ void mma_f16(float c[4], const unsigned a[4],
                                        unsigned b0, unsigned b1) {
    asm volatile(
        "mma.sync.aligned.m16n8k16.row.col.f32.f16.f16.f32 "
        "{%0,%1,%2,%3}, {%4,%5,%6,%7}, {%8,%9}, {%0,%1,%2,%3};"
        : "+f"(c[0]), "+f"(c[1]), "+f"(c[2]), "+f"(c[3])
        : "r"(a[0]), "r"(a[1]), "r"(a[2]), "r"(a[3]), "r"(b0), "r"(b1));
}

__device__ __forceinline__ void cp16(void* smem, const void* gmem) {
    unsigned s = (unsigned)__cvta_generic_to_shared(smem);
    asm volatile("cp.async.ca.shared.global [%0], [%1], 16;\n"
                 :: "r"(s), "l"(gmem));
}
#define CP_COMMIT() asm volatile("cp.async.commit_group;\n")
#define CP_WAIT(n)  asm volatile("cp.async.wait_group %0;\n" :: "n"(n))

__device__ __forceinline__ unsigned f2_to_h2(float a, float b) {
    __half2 h = __floats2half2_rn(a, b);
    return *(const unsigned*)&h;
}

// ---------------------------------------------------------------------------
// Convert kernel (R14 layout — fastest measured): value -> transposed fp16
// cache; Q -> fp16; W -> fp16. Each thread: 4 consecutive float4 (64B in,
// 32B out). grid = 4792 x 256, exact cover.
// ---------------------------------------------------------------------------
__global__ __launch_bounds__(256) void convert_kernel(
    const float* __restrict__ value,
    const float* __restrict__ Q,
    const float* __restrict__ Woff,
    const float* __restrict__ Wattn)
{
    int T = blockIdx.x * 256 + threadIdx.x;
    float4 v[4];
    uint4* dst;
    if (T < V_QUADS) {
        int c4b = (4 * T) & 7;            // {0,4}
        int h   = (T >> 1) & 7;
        int pb  = T >> 4;                 // b*TOTV + pos
        int b   = (pb >= TOTV) ? 1 : 0;
        int pos = pb - b * TOTV;
        const float4* src = (const float4*)(value
            + ((size_t)pb * 8 + h) * 32 + c4b * 4);
#pragma unroll
        for (int j = 0; j < 4; j++) v[j] = src[j];
        dst = (uint4*)((uint2*)g_vcache
            + ((size_t)(b * 8 + h) * TOTV + pos) * 8 + c4b);
    } else if (T < V_QUADS + Q_QUADS) {
        int i = T - V_QUADS;
        const float4* src = (const float4*)Q + 4 * i;
#pragma unroll
        for (int j = 0; j < 4; j++) v[j] = src[j];
        dst = (uint4*)g_qh + 2 * i;
    } else {
        int i = T - V_QUADS - Q_QUADS;    // 0..6143
        const float4* src = (i < 4096) ? ((const float4*)Woff + 4 * i)
                                       : ((const float4*)Wattn + 4 * (i - 4096));
#pragma unroll
        for (int j = 0; j < 4; j++) v[j] = src[j];
        dst = (uint4*)g_wh + 2 * i;
    }
    uint4 o0, o1;
    o0.x = f2_to_h2(v[0].x, v[0].y); o0.y = f2_to_h2(v[0].z, v[0].w);
    o0.z = f2_to_h2(v[1].x, v[1].y); o0.w = f2_to_h2(v[1].z, v[1].w);
    o1.x = f2_to_h2(v[2].x, v[2].y); o1.y = f2_to_h2(v[2].z, v[2].w);
    o1.z = f2_to_h2(v[3].x, v[3].y); o1.w = f2_to_h2(v[3].z, v[3].w);
    dst[0] = o0;
    dst[1] = o1;
}

// ---------------------------------------------------------------------------
// GEMM: C[m,n] = sum_k Qh[m,k]*Wh[n,k] + bias[n], fp16 in, f32 accum.
// BM=BN=128, BK=32; cp.async 3-STAGE pipeline; coalesced smem-staged
// epilogue. 8 warps (4m x 2n). grid = (256, 3).
// ---------------------------------------------------------------------------
__global__ __launch_bounds__(256) void gemm_kernel(
    const float* __restrict__ boff,
    const float* __restrict__ battn)
{
    extern __shared__ __align__(16) char sraw[];
    float (*eb)[132] = reinterpret_cast<float(*)[132]>(sraw);    // 64x132 alias

    const int tid  = threadIdx.x;
    const int m0   = blockIdx.x * 128;
    const int n0   = blockIdx.y * 128;
    const int warp = tid >> 5, lane = tid & 31;
    const int wm   = (warp & 3) * 32;
    const int wn   = (warp >> 2) * 64;
    const int g    = lane >> 2;
    const int tg   = lane & 3;

    const int r0 = tid >> 2, c0 = (tid & 3) * 8;
    const int r1 = (tid + 256) >> 2, c1 = c0;

    float acc[2][8][4];
#pragma unroll
    for (int mi = 0; mi < 2; mi++)
#pragma unroll
        for (int ni = 0; ni < 8; ni++)
#pragma unroll
            for (int k = 0; k < 4; k++) acc[mi][ni][k] = 0.f;

    const __half* Abase = g_qh + (size_t)m0 * 256;
    const __half* Bbase = g_wh + (size_t)n0 * 256;

#pragma unroll
    for (int pk = 0; pk < 2; pk++) {
        __half (*Asb)[40] = (__half(*)[40])(sraw + pk * 20480);
        __half (*Bsb)[40] = (__half(*)[40])(sraw + pk * 20480 + 10240);
        int ko = pk * 32;
        cp16(&Asb[r0][c0], Abase + r0 * 256 + ko + c0);
        cp16(&Asb[r1][c1], Abase + r1 * 256 + ko + c1);
        cp16(&Bsb[r0][c0], Bbase + r0 * 256 + ko + c0);
        cp16(&Bsb[r1][c1], Bbase + r1 * 256 + ko + c1);
        CP_COMMIT();
    }

#pragma unroll
    for (int kt = 0; kt < 8; kt++) {
        if (kt < 7) { CP_WAIT(1); } else { CP_WAIT(0); }
        __syncthreads();
        if (kt < 6) {
            int st = (kt + 2) % 3, ko = (kt + 2) * 32;
            __half (*Asb)[40] = (__half(*)[40])(sraw + st * 20480);
            __half (*Bsb)[40] = (__half(*)[40])(sraw + st * 20480 + 10240);
            cp16(&Asb[r0][c0], Abase + r0 * 256 + ko + c0);
            cp16(&Asb[r1][c1], Abase + r1 * 256 + ko + c1);
            cp16(&Bsb[r0][c0], Bbase + r0 * 256 + ko + c0);
            cp16(&Bsb[r1][c1], Bbase + r1 * 256 + ko + c1);
            CP_COMMIT();
        }
        const int s = kt % 3;
        __half (*As)[40] = (__half(*)[40])(sraw + s * 20480);
        __half (*Bs)[40] = (__half(*)[40])(sraw + s * 20480 + 10240);
#pragma unroll
        for (int ks = 0; ks < 32; ks += 16) {
            unsigned a[2][4];
#pragma unroll
            for (int mi = 0; mi < 2; mi++) {
                int r = wm + mi * 16 + g;
                a[mi][0] = *(const unsigned*)(&As[r][ks + 2 * tg]);
                a[mi][1] = *(const unsigned*)(&As[r + 8][ks + 2 * tg]);
                a[mi][2] = *(const unsigned*)(&As[r][ks + 2 * tg + 8]);
                a[mi][3] = *(const unsigned*)(&As[r + 8][ks + 2 * tg + 8]);
            }
#pragma unroll
            for (int ni = 0; ni < 8; ni++) {
                unsigned b0 = *(const unsigned*)(&Bs[wn + ni * 8 + g][ks + 2 * tg]);
                unsigned b1 = *(const unsigned*)(&Bs[wn + ni * 8 + g][ks + 2 * tg + 8]);
                mma_f16(acc[0][ni], a[0], b0, b1);
                mma_f16(acc[1][ni], a[1], b0, b1);
            }
        }
    }

    // ---- coalesced epilogue: two 64-row chunks through smem ----
#pragma unroll
    for (int half = 0; half < 2; half++) {
        const int rbase = half * 64;
        __syncthreads();
        if ((wm & 64) == rbase) {
#pragma unroll
            for (int mi = 0; mi < 2; mi++) {
                int r = (wm & 32) + mi * 16 + g;
#pragma unroll
                for (int ni = 0; ni < 8; ni++) {
                    int col  = wn + ni * 8 + 2 * tg;
                    int gcol = n0 + col;
                    float b0v = (gcol < 256) ? boff[gcol] : battn[gcol - 256];
                    float b1v = (gcol + 1 < 256) ? boff[gcol + 1]
                                                 : battn[gcol + 1 - 256];
                    eb[r][col]         = acc[mi][ni][0] + b0v;
                    eb[r][col + 1]     = acc[mi][ni][1] + b1v;
                    eb[r + 8][col]     = acc[mi][ni][2] + b0v;
                    eb[r + 8][col + 1] = acc[mi][ni][3] + b1v;
                }
            }
        }
        __syncthreads();
#pragma unroll
        for (int i = 0; i < 8; i++) {
            int idx = tid + i * 256;
            int r = idx >> 5;
            int c = (idx & 31) * 4;
            float4 v = *(const float4*)(&eb[r][c]);
            *(float4*)(g_scratch + (size_t)(m0 + rbase + r) * NOUT + n0 + c) = v;
        }
    }
}

// one-time: allow 60KB dynamic smem on gemm_kernel
namespace {
struct _AthenaInit {
    _AthenaInit() {
        cudaFuncSetAttribute(gemm_kernel,
                             cudaFuncAttributeMaxDynamicSharedMemorySize,
                             GEMM_SMEM);
    }
};
_AthenaInit _athena_init;
}

// ---------------------------------------------------------------------------
// MSDA kernel: 2 queries per warp, 512-thread blocks. NEW: 4 records per
// (query, point) — one per (row,col) tap — carrying {offset, weight as f32
// bits}, so the gather loop needs no weight shift/convert (18 instr/iter).
// Lane = {qh=bit4, combo=bits2-3 (row*2+col), chgroup=bits0-1}.
// grid = (NQ/32, NH, BS) = (512, 8, 2).
// ---------------------------------------------------------------------------
__global__ __launch_bounds__(512) void msda_kernel(
    const float* __restrict__ refp,
    float* __restrict__ out)
{
    const int b    = blockIdx.z;
    const int h    = blockIdx.y;
    const int warp = threadIdx.x >> 5;     // 0..15
    const int lane = threadIdx.x & 31;
    const int qh   = lane >> 4;
    const int pt   = lane & 15;
    const int q    = blockIdx.x * 32 + warp * 2 + qh;
    const int qg   = b * NQ + q;

    const float* sc = g_scratch + (size_t)qg * NOUT;

    const int l  = pt >> 2;
    const int p  = pt & 3;
    const int Wl = 128 >> l;
    const int start = (l == 0) ? 0 : (l == 1) ? 16384 : (l == 2) ? 20480 : 21504;

    // ---- softmax over 16 logits (within this half's query) ----
    float lg = sc[256 + h * 16 + pt];
    float mx = lg;
#pragma unroll
    for (int o = 8; o; o >>= 1)
        mx = fmaxf(mx, __shfl_xor_sync(0xffffffffu, mx, o));
    float e = __expf(lg - mx);
    float s = e;
#pragma unroll
    for (int o = 8; o; o >>= 1)
        s += __shfl_xor_sync(0xffffffffu, s, o);
    float w = e / s;

    // ---- tap geometry + folded weights for point pt of this query ----
    float2 of = ((const float2*)(sc + h * 32))[pt];
    float2 rp = ((const float2*)(refp + (size_t)qg * 8))[p];

    float x = rp.x * (float)Wl + of.x - 0.5f;
    float y = rp.y * (float)Wl + of.y - 0.5f;
    float xf = floorf(x), yf = floorf(y);
    float fx = x - xf, fy = y - yf;
    int ix = (int)xf, iy = (int)yf;
    int ixb = min(max(ix, 0), Wl - 2);
    int iyb = min(max(iy, 0), Wl - 2);

    float cw0 = (ixb == ix) ? (1.f - fx) : (ixb == ix + 1) ? fx : 0.f;
    float cw1 = (ixb + 1 == ix) ? (1.f - fx) : (ixb + 1 == ix + 1) ? fx : 0.f;
    float rw0 = (iyb == iy) ? (1.f - fy) : (iyb == iy + 1) ? fy : 0.f;
    float rw1 = (iyb + 1 == iy) ? (1.f - fy) : (iyb + 1 == iy + 1) ? fy : 0.f;

    float wr0 = w * rw0, wr1 = w * rw1;
    unsigned offA = (unsigned)(start + iyb * Wl + ixb) * 64u;
    unsigned offB = offA + (unsigned)Wl * 64u;

    // ---- smem records: rec[warp][qh][row*2+col][pt], stride 17 ----
    __shared__ uint2 rec[16][2][4][17];
    {
        uint2 r00; r00.x = offA;      r00.y = __float_as_uint(wr0 * cw0);
        uint2 r01; r01.x = offA + 64; r01.y = __float_as_uint(wr0 * cw1);
        uint2 r10; r10.x = offB;      r10.y = __float_as_uint(wr1 * cw0);
        uint2 r11; r11.x = offB + 64; r11.y = __float_as_uint(wr1 * cw1);
        rec[warp][qh][0][pt] = r00;
        rec[warp][qh][1][pt] = r01;
        rec[warp][qh][2][pt] = r10;
        rec[warp][qh][3][pt] = r11;
    }
    __syncwarp();

    // ---- gather loop ----
    const int combo = (lane >> 2) & 3;            // row*2 + col
    const uint2* recq = &rec[warp][qh][combo][0];
    // (lane&3)*16 = chgroup only; col lives in the record offset
    const char* vbase = (const char*)g_vcache
        + (size_t)(b * NH + h) * TOTV * 64 + (lane & 3) * 16;

    float a0 = 0.f, a1 = 0.f, a2 = 0.f, a3 = 0.f;
    float a4 = 0.f, a5 = 0.f, a6 = 0.f, a7 = 0.f;
#pragma unroll
    for (int i = 0; i < 16; i++) {
        uint2 ei = recq[i];                             // LDS.64 broadcast x4
        uint4 v  = __ldg((const uint4*)(vbase + ei.x)); // 8 channels
        float wt = __uint_as_float(ei.y);               // ready-to-use weight
        float2 f0 = __half22float2(*(const __half2*)&v.x);
        float2 f1 = __half22float2(*(const __half2*)&v.y);
        float2 f2 = __half22float2(*(const __half2*)&v.z);
        float2 f3 = __half22float2(*(const __half2*)&v.w);
        a0 += wt * f0.x; a1 += wt * f0.y;
        a2 += wt * f1.x; a3 += wt * f1.y;
        a4 += wt * f2.x; a5 += wt * f2.y;
        a6 += wt * f3.x; a7 += wt * f3.y;
    }
    // reduce over col (xor 4) then row (xor 8); stays within the half
#pragma unroll
    for (int o = 4; o <= 8; o <<= 1) {
        a0 += __shfl_xor_sync(0xffffffffu, a0, o);
        a1 += __shfl_xor_sync(0xffffffffu, a1, o);
        a2 += __shfl_xor_sync(0xffffffffu, a2, o);
        a3 += __shfl_xor_sync(0xffffffffu, a3, o);
        a4 += __shfl_xor_sync(0xffffffffu, a4, o);
        a5 += __shfl_xor_sync(0xffffffffu, a5, o);
        a6 += __shfl_xor_sync(0xffffffffu, a6, o);
        a7 += __shfl_xor_sync(0xffffffffu, a7, o);
    }

    // ---- smem transpose: sm[channel][q_local], 32 queries per block ----
    __shared__ float sm[32][36];
    if ((lane & 12) == 0) {                 // lanes 0-3 / 16-19
        int ch = (lane & 3) * 8;
        int qc = warp * 2 + qh;
        sm[ch + 0][qc] = a0; sm[ch + 1][qc] = a1;
        sm[ch + 2][qc] = a2; sm[ch + 3][qc] = a3;
        sm[ch + 4][qc] = a4; sm[ch + 5][qc] = a5;
        sm[ch + 6][qc] = a6; sm[ch + 7][qc] = a7;
    }
    __syncthreads();
    int ch = threadIdx.x >> 4;
    int qi = (threadIdx.x & 15) * 2;
    float2 o2;
    o2.x = sm[ch][qi];
    o2.y = sm[ch][qi + 1];
    *(float2*)(out + ((size_t)(b * 256 + h * 32 + ch)) * NQ
               + blockIdx.x * 32 + qi) = o2;
}

// ---------------------------------------------------------------------------
// Launch
// ---------------------------------------------------------------------------
extern "C" void kernel_launch(void* const* d_in, const int* in_sizes, int n_in,
                              void* d_out, int out_size) {
    const float* query = (const float*)d_in[0];
    const float* value = (const float*)d_in[1];
    const float* refp  = (const float*)d_in[2];
    const float* Woff  = (const float*)d_in[3];
    const float* boff  = (const float*)d_in[4];
    const float* Wattn = (const float*)d_in[5];
    const float* battn = (const float*)d_in[6];
    float* out = (float*)d_out;

    convert_kernel<<<CONV_GRID, 256>>>(value, query, Woff, Wattn);

    dim3 ggrid(M_TOT / 128, 3);
    gemm_kernel<<<ggrid, 256, GEMM_SMEM>>>(boff, battn);

    dim3 mgrid(NQ / 32, NH, BS);
    msda_kernel<<<mgrid, 512>>>(refp, out);
}

// round 17
// speedup vs baseline: 1.0864x; 1.0162x over previous
#include <cuda_runtime.h>
#include <cuda_fp16.h>
#include <cstdint>
#include <math.h>

// ---------------------------------------------------------------------------
// Problem constants
// ---------------------------------------------------------------------------
#define BS   2
#define NQ   16384
#define E    256
#define NH   8
#define NL   4
#define NP   4
#define TOTV 21760
#define NOUT 384
#define M_TOT (BS * NQ)

// convert quads (each thread processes 4 float4 = 64B in, 32B out)
#define V_QUADS (BS * TOTV * NH * 2)      // 696,320
#define Q_QUADS (M_TOT * E / 16)          // 524,288
#define W_QUADS (384 * 256 / 16)          // 6,144
#define CONV_QUADS (V_QUADS + Q_QUADS + W_QUADS)   // 1,226,752
#define CONV_GRID  (CONV_QUADS / 256)     // 4792 exact

#define GEMM_SMEM  61440                  // 3 stages x 20KB

// GEMM scratch [32768][384] f32
__device__ float g_scratch[(size_t)M_TOT * NOUT];
// fp16 value cache, transposed: [b][h][pos][32ch]
__device__ __align__(128) __half g_vcache[(size_t)BS * NH * TOTV * 32];
// fp16 copies of Q and W (W rows 0-255 = W_off, 256-383 = W_attn)
__device__ __align__(128) __half g_qh[(size_t)M_TOT * E];
__device__ __align__(128) __half g_wh[(size_t)384 * 256];

// ---------------------------------------------------------------------------
// helpers
// ---------------------------------------------------------------------------
__device__ __forceinline__ void mma_f16(float c[4], const unsigned a[4],
                                        unsigned b0, unsigned b1) {
    asm volatile(
        "mma.sync.aligned.m16n8k16.row.col.f32.f16.f16.f32 "
        "{%0,%1,%2,%3}, {%4,%5,%6,%7}, {%8,%9}, {%0,%1,%2,%3};"
        : "+f"(c[0]), "+f"(c[1]), "+f"(c[2]), "+f"(c[3])
        : "r"(a[0]), "r"(a[1]), "r"(a[2]), "r"(a[3]), "r"(b0), "r"(b1));
}

__device__ __forceinline__ void cp16(void* smem, const void* gmem) {
    unsigned s = (unsigned)__cvta_generic_to_shared(smem);
    asm volatile("cp.async.ca.shared.global [%0], [%1], 16;\n"
                 :: "r"(s), "l"(gmem));
}
#define CP_COMMIT() asm volatile("cp.async.commit_group;\n")
#define CP_WAIT(n)  asm volatile("cp.async.wait_group %0;\n" :: "n"(n))

__device__ __forceinline__ unsigned f2_to_h2(float a, float b) {
    __half2 h = __floats2half2_rn(a, b);
    return *(const unsigned*)&h;
}

// ---------------------------------------------------------------------------
// Convert kernel (R14 layout): value -> transposed fp16 cache; Q -> fp16;
// W -> fp16. Each thread: 4 consecutive float4 (64B in, 32B out).
// grid = 4792 x 256, exact cover.
// ---------------------------------------------------------------------------
__global__ __launch_bounds__(256) void convert_kernel(
    const float* __restrict__ value,
    const float* __restrict__ Q,
    const float* __restrict__ Woff,
    const float* __restrict__ Wattn)
{
    int T = blockIdx.x * 256 + threadIdx.x;
    float4 v[4];
    uint4* dst;
    if (T < V_QUADS) {
        int c4b = (4 * T) & 7;            // {0,4}
        int h   = (T >> 1) & 7;
        int pb  = T >> 4;                 // b*TOTV + pos
        int b   = (pb >= TOTV) ? 1 : 0;
        int pos = pb - b * TOTV;
        const float4* src = (const float4*)(value
            + ((size_t)pb * 8 + h) * 32 + c4b * 4);
#pragma unroll
        for (int j = 0; j < 4; j++) v[j] = src[j];
        dst = (uint4*)((uint2*)g_vcache
            + ((size_t)(b * 8 + h) * TOTV + pos) * 8 + c4b);
    } else if (T < V_QUADS + Q_QUADS) {
        int i = T - V_QUADS;
        const float4* src = (const float4*)Q + 4 * i;
#pragma unroll
        for (int j = 0; j < 4; j++) v[j] = src[j];
        dst = (uint4*)g_qh + 2 * i;
    } else {
        int i = T - V_QUADS - Q_QUADS;    // 0..6143
        const float4* src = (i < 4096) ? ((const float4*)Woff + 4 * i)
                                       : ((const float4*)Wattn + 4 * (i - 4096));
#pragma unroll
        for (int j = 0; j < 4; j++) v[j] = src[j];
        dst = (uint4*)g_wh + 2 * i;
    }
    uint4 o0, o1;
    o0.x = f2_to_h2(v[0].x, v[0].y); o0.y = f2_to_h2(v[0].z, v[0].w);
    o0.z = f2_to_h2(v[1].x, v[1].y); o0.w = f2_to_h2(v[1].z, v[1].w);
    o1.x = f2_to_h2(v[2].x, v[2].y); o1.y = f2_to_h2(v[2].z, v[2].w);
    o1.z = f2_to_h2(v[3].x, v[3].y); o1.w = f2_to_h2(v[3].z, v[3].w);
    dst[0] = o0;
    dst[1] = o1;
}

// ---------------------------------------------------------------------------
// GEMM: C[m,n] = sum_k Qh[m,k]*Wh[n,k] + bias[n], fp16 in, f32 accum.
// BM=BN=128, BK=32; cp.async 3-STAGE pipeline; coalesced smem-staged
// epilogue. 8 warps (4m x 2n). grid = (256, 3).
// ---------------------------------------------------------------------------
__global__ __launch_bounds__(256) void gemm_kernel(
    const float* __restrict__ boff,
    const float* __restrict__ battn)
{
    extern __shared__ __align__(16) char sraw[];
    float (*eb)[132] = reinterpret_cast<float(*)[132]>(sraw);    // 64x132 alias

    const int tid  = threadIdx.x;
    const int m0   = blockIdx.x * 128;
    const int n0   = blockIdx.y * 128;
    const int warp = tid >> 5, lane = tid & 31;
    const int wm   = (warp & 3) * 32;
    const int wn   = (warp >> 2) * 64;
    const int g    = lane >> 2;
    const int tg   = lane & 3;

    const int r0 = tid >> 2, c0 = (tid & 3) * 8;
    const int r1 = (tid + 256) >> 2, c1 = c0;

    float acc[2][8][4];
#pragma unroll
    for (int mi = 0; mi < 2; mi++)
#pragma unroll
        for (int ni = 0; ni < 8; ni++)
#pragma unroll
            for (int k = 0; k < 4; k++) acc[mi][ni][k] = 0.f;

    const __half* Abase = g_qh + (size_t)m0 * 256;
    const __half* Bbase = g_wh + (size_t)n0 * 256;

#pragma unroll
    for (int pk = 0; pk < 2; pk++) {
        __half (*Asb)[40] = (__half(*)[40])(sraw + pk * 20480);
        __half (*Bsb)[40] = (__half(*)[40])(sraw + pk * 20480 + 10240);
        int ko = pk * 32;
        cp16(&Asb[r0][c0], Abase + r0 * 256 + ko + c0);
        cp16(&Asb[r1][c1], Abase + r1 * 256 + ko + c1);
        cp16(&Bsb[r0][c0], Bbase + r0 * 256 + ko + c0);
        cp16(&Bsb[r1][c1], Bbase + r1 * 256 + ko + c1);
        CP_COMMIT();
    }

#pragma unroll
    for (int kt = 0; kt < 8; kt++) {
        if (kt < 7) { CP_WAIT(1); } else { CP_WAIT(0); }
        __syncthreads();
        if (kt < 6) {
            int st = (kt + 2) % 3, ko = (kt + 2) * 32;
            __half (*Asb)[40] = (__half(*)[40])(sraw + st * 20480);
            __half (*Bsb)[40] = (__half(*)[40])(sraw + st * 20480 + 10240);
            cp16(&Asb[r0][c0], Abase + r0 * 256 + ko + c0);
            cp16(&Asb[r1][c1], Abase + r1 * 256 + ko + c1);
            cp16(&Bsb[r0][c0], Bbase + r0 * 256 + ko + c0);
            cp16(&Bsb[r1][c1], Bbase + r1 * 256 + ko + c1);
            CP_COMMIT();
        }
        const int s = kt % 3;
        __half (*As)[40] = (__half(*)[40])(sraw + s * 20480);
        __half (*Bs)[40] = (__half(*)[40])(sraw + s * 20480 + 10240);
#pragma unroll
        for (int ks = 0; ks < 32; ks += 16) {
            unsigned a[2][4];
#pragma unroll
            for (int mi = 0; mi < 2; mi++) {
                int r = wm + mi * 16 + g;
                a[mi][0] = *(const unsigned*)(&As[r][ks + 2 * tg]);
                a[mi][1] = *(const unsigned*)(&As[r + 8][ks + 2 * tg]);
                a[mi][2] = *(const unsigned*)(&As[r][ks + 2 * tg + 8]);
                a[mi][3] = *(const unsigned*)(&As[r + 8][ks + 2 * tg + 8]);
            }
#pragma unroll
            for (int ni = 0; ni < 8; ni++) {
                unsigned b0 = *(const unsigned*)(&Bs[wn + ni * 8 + g][ks + 2 * tg]);
                unsigned b1 = *(const unsigned*)(&Bs[wn + ni * 8 + g][ks + 2 * tg + 8]);
                mma_f16(acc[0][ni], a[0], b0, b1);
                mma_f16(acc[1][ni], a[1], b0, b1);
            }
        }
    }

    // ---- coalesced epilogue: two 64-row chunks through smem ----
#pragma unroll
    for (int half = 0; half < 2; half++) {
        const int rbase = half * 64;
        __syncthreads();
        if ((wm & 64) == rbase) {
#pragma unroll
            for (int mi = 0; mi < 2; mi++) {
                int r = (wm & 32) + mi * 16 + g;
#pragma unroll
                for (int ni = 0; ni < 8; ni++) {
                    int col  = wn + ni * 8 + 2 * tg;
                    int gcol = n0 + col;
                    float b0v = (gcol < 256) ? boff[gcol] : battn[gcol - 256];
                    float b1v = (gcol + 1 < 256) ? boff[gcol + 1]
                                                 : battn[gcol + 1 - 256];
                    eb[r][col]         = acc[mi][ni][0] + b0v;
                    eb[r][col + 1]     = acc[mi][ni][1] + b1v;
                    eb[r + 8][col]     = acc[mi][ni][2] + b0v;
                    eb[r + 8][col + 1] = acc[mi][ni][3] + b1v;
                }
            }
        }
        __syncthreads();
#pragma unroll
        for (int i = 0; i < 8; i++) {
            int idx = tid + i * 256;
            int r = idx >> 5;
            int c = (idx & 31) * 4;
            float4 v = *(const float4*)(&eb[r][c]);
            *(float4*)(g_scratch + (size_t)(m0 + rbase + r) * NOUT + n0 + c) = v;
        }
    }
}

// one-time: allow 60KB dynamic smem on gemm_kernel
namespace {
struct _AthenaInit {
    _AthenaInit() {
        cudaFuncSetAttribute(gemm_kernel,
                             cudaFuncAttributeMaxDynamicSharedMemorySize,
                             GEMM_SMEM);
    }
};
_AthenaInit _athena_init;
}

// ---------------------------------------------------------------------------
// MSDA kernel: 2 queries per warp, 512-thread blocks, 4-record layout.
// NEW (retry at 512 threads): HFMA2 accumulation — records carry the folded
// tap weight as duplicated half2, loop = LDS.64 + LDG.128 + 4 HFMA2.
// Two half2 accumulator banks (8 taps each), fp32 combine before reduce.
// Lane = {qh=bit4, combo=bits2-3 (row*2+col), chgroup=bits0-1}.
// grid = (NQ/32, NH, BS) = (512, 8, 2).
// ---------------------------------------------------------------------------
__global__ __launch_bounds__(512) void msda_kernel(
    const float* __restrict__ refp,
    float* __restrict__ out)
{
    const int b    = blockIdx.z;
    const int h    = blockIdx.y;
    const int warp = threadIdx.x >> 5;     // 0..15
    const int lane = threadIdx.x & 31;
    const int qh   = lane >> 4;
    const int pt   = lane & 15;
    const int q    = blockIdx.x * 32 + warp * 2 + qh;
    const int qg   = b * NQ + q;

    const float* sc = g_scratch + (size_t)qg * NOUT;

    const int l  = pt >> 2;
    const int p  = pt & 3;
    const int Wl = 128 >> l;
    const int start = (l == 0) ? 0 : (l == 1) ? 16384 : (l == 2) ? 20480 : 21504;

    // ---- softmax over 16 logits (within this half's query) ----
    float lg = sc[256 + h * 16 + pt];
    float mx = lg;
#pragma unroll
    for (int o = 8; o; o >>= 1)
        mx = fmaxf(mx, __shfl_xor_sync(0xffffffffu, mx, o));
    float e = __expf(lg - mx);
    float s = e;
#pragma unroll
    for (int o = 8; o; o >>= 1)
        s += __shfl_xor_sync(0xffffffffu, s, o);
    float w = e / s;

    // ---- tap geometry + folded weights for point pt of this query ----
    float2 of = ((const float2*)(sc + h * 32))[pt];
    float2 rp = ((const float2*)(refp + (size_t)qg * 8))[p];

    float x = rp.x * (float)Wl + of.x - 0.5f;
    float y = rp.y * (float)Wl + of.y - 0.5f;
    float xf = floorf(x), yf = floorf(y);
    float fx = x - xf, fy = y - yf;
    int ix = (int)xf, iy = (int)yf;
    int ixb = min(max(ix, 0), Wl - 2);
    int iyb = min(max(iy, 0), Wl - 2);

    float cw0 = (ixb == ix) ? (1.f - fx) : (ixb == ix + 1) ? fx : 0.f;
    float cw1 = (ixb + 1 == ix) ? (1.f - fx) : (ixb + 1 == ix + 1) ? fx : 0.f;
    float rw0 = (iyb == iy) ? (1.f - fy) : (iyb == iy + 1) ? fy : 0.f;
    float rw1 = (iyb + 1 == iy) ? (1.f - fy) : (iyb + 1 == iy + 1) ? fy : 0.f;

    float wr0 = w * rw0, wr1 = w * rw1;
    unsigned offA = (unsigned)(start + iyb * Wl + ixb) * 64u;
    unsigned offB = offA + (unsigned)Wl * 64u;

    // ---- smem records: rec[warp][qh][row*2+col][pt], stride 17 ----
    __shared__ uint2 rec[16][2][4][17];
    {
        float w00 = wr0 * cw0, w01 = wr0 * cw1;
        float w10 = wr1 * cw0, w11 = wr1 * cw1;
        uint2 r00; r00.x = offA;      r00.y = f2_to_h2(w00, w00);
        uint2 r01; r01.x = offA + 64; r01.y = f2_to_h2(w01, w01);
        uint2 r10; r10.x = offB;      r10.y = f2_to_h2(w10, w10);
        uint2 r11; r11.x = offB + 64; r11.y = f2_to_h2(w11, w11);
        rec[warp][qh][0][pt] = r00;
        rec[warp][qh][1][pt] = r01;
        rec[warp][qh][2][pt] = r10;
        rec[warp][qh][3][pt] = r11;
    }
    __syncwarp();

    // ---- gather loop: HFMA2 accumulation, two banks ----
    const int combo = (lane >> 2) & 3;            // row*2 + col
    const uint2* recq = &rec[warp][qh][combo][0];
    const char* vbase = (const char*)g_vcache
        + (size_t)(b * NH + h) * TOTV * 64 + (lane & 3) * 16;

    __half2 cA0 = __float2half2_rn(0.f), cA1 = cA0, cA2 = cA0, cA3 = cA0;
    __half2 cB0 = cA0, cB1 = cA0, cB2 = cA0, cB3 = cA0;
#pragma unroll
    for (int i = 0; i < 8; i++) {
        uint2 ei = recq[i];
        uint4 v  = __ldg((const uint4*)(vbase + ei.x));
        __half2 wt = *(const __half2*)&ei.y;
        cA0 = __hfma2(*(const __half2*)&v.x, wt, cA0);
        cA1 = __hfma2(*(const __half2*)&v.y, wt, cA1);
        cA2 = __hfma2(*(const __half2*)&v.z, wt, cA2);
        cA3 = __hfma2(*(const __half2*)&v.w, wt, cA3);
    }
#pragma unroll
    for (int i = 8; i < 16; i++) {
        uint2 ei = recq[i];
        uint4 v  = __ldg((const uint4*)(vbase + ei.x));
        __half2 wt = *(const __half2*)&ei.y;
        cB0 = __hfma2(*(const __half2*)&v.x, wt, cB0);
        cB1 = __hfma2(*(const __half2*)&v.y, wt, cB1);
        cB2 = __hfma2(*(const __half2*)&v.z, wt, cB2);
        cB3 = __hfma2(*(const __half2*)&v.w, wt, cB3);
    }

    // ---- fp32 combine of the two banks ----
    float2 fA0 = __half22float2(cA0), fB0 = __half22float2(cB0);
    float2 fA1 = __half22float2(cA1), fB1 = __half22float2(cB1);
    float2 fA2 = __half22float2(cA2), fB2 = __half22float2(cB2);
    float2 fA3 = __half22float2(cA3), fB3 = __half22float2(cB3);
    float a0 = fA0.x + fB0.x, a1 = fA0.y + fB0.y;
    float a2 = fA1.x + fB1.x, a3 = fA1.y + fB1.y;
    float a4 = fA2.x + fB2.x, a5 = fA2.y + fB2.y;
    float a6 = fA3.x + fB3.x, a7 = fA3.y + fB3.y;

    // reduce over col (xor 4) then row (xor 8); stays within the half
#pragma unroll
    for (int o = 4; o <= 8; o <<= 1) {
        a0 += __shfl_xor_sync(0xffffffffu, a0, o);
        a1 += __shfl_xor_sync(0xffffffffu, a1, o);
        a2 += __shfl_xor_sync(0xffffffffu, a2, o);
        a3 += __shfl_xor_sync(0xffffffffu, a3, o);
        a4 += __shfl_xor_sync(0xffffffffu, a4, o);
        a5 += __shfl_xor_sync(0xffffffffu, a5, o);
        a6 += __shfl_xor_sync(0xffffffffu, a6, o);
        a7 += __shfl_xor_sync(0xffffffffu, a7, o);
    }

    // ---- smem transpose: sm[channel][q_local], 32 queries per block ----
    __shared__ float sm[32][36];
    if ((lane & 12) == 0) {                 // lanes 0-3 / 16-19
        int ch = (lane & 3) * 8;
        int qc = warp * 2 + qh;
        sm[ch + 0][qc] = a0; sm[ch + 1][qc] = a1;
        sm[ch + 2][qc] = a2; sm[ch + 3][qc] = a3;
        sm[ch + 4][qc] = a4; sm[ch + 5][qc] = a5;
        sm[ch + 6][qc] = a6; sm[ch + 7][qc] = a7;
    }
    __syncthreads();
    int ch = threadIdx.x >> 4;
    int qi = (threadIdx.x & 15) * 2;
    float2 o2;
    o2.x = sm[ch][qi];
    o2.y = sm[ch][qi + 1];
    *(float2*)(out + ((size_t)(b * 256 + h * 32 + ch)) * NQ
               + blockIdx.x * 32 + qi) = o2;
}

// ---------------------------------------------------------------------------
// Launch
// ---------------------------------------------------------------------------
extern "C" void kernel_launch(void* const* d_in, const int* in_sizes, int n_in,
                              void* d_out, int out_size) {
    const float* query = (const float*)d_in[0];
    const float* value = (const float*)d_in[1];
    const float* refp  = (const float*)d_in[2];
    const float* Woff  = (const float*)d_in[3];
    const float* boff  = (const float*)d_in[4];
    const float* Wattn = (const float*)d_in[5];
    const float* battn = (const float*)d_in[6];
    float* out = (float*)d_out;

    convert_kernel<<<CONV_GRID, 256>>>(value, query, Woff, Wattn);

    dim3 ggrid(M_TOT / 128, 3);
    gemm_kernel<<<ggrid, 256, GEMM_SMEM>>>(boff, battn);

    dim3 mgrid(NQ / 32, NH, BS);
    msda_kernel<<<mgrid, 512>>>(refp, out);
}